// round 2
// baseline (speedup 1.0000x reference)
#include <cuda_runtime.h>
#include <cuda_bf16.h>
#include <cstdint>

// Problem constants
#define BB 32
#define TT 512
#define II 512
#define HH 512
#define G4H 2048
#define EE 4
#define OUTD 512
#define NPAIR 64     // B * TOPK, always exactly 64 (softmax probs > 0)
#define NCHAIN 128   // NPAIR * 2 directions

// ---------------- device scratch (static; no allocations allowed) -------------
__device__ __align__(16) float g_xp[(size_t)NCHAIN * TT * G4H];       // 512 MB
__device__ __align__(16) float g_hout[(size_t)NPAIR * TT * 2 * HH];   // 128 MB
__device__ __align__(16) float g_combined[(size_t)BB * TT * 2 * HH];  // 64 MB
__device__ __align__(16) float g_hbuf[2][NCHAIN * HH];
__device__ __align__(16) float g_cbuf[NCHAIN * HH];
__device__ __align__(16) float g_router_in[BB * II];
__device__ __align__(16) float g_router_h[BB * II];
__device__ int   g_pair_b[NPAIR];
__device__ int   g_pair_e[NPAIR];
__device__ int   g_off[EE];
__device__ int   g_cnt[EE];
__device__ int   g_bpair[BB * 2];
__device__ float g_bw[BB * 2];
__device__ float g_lb;

// fast sigmoid via MUFU.TANH
__device__ __forceinline__ float sigmoid_fast(float x) {
    return 0.5f * __tanhf(0.5f * x) + 0.5f;
}

// ---------------- router ------------------------------------------------------
__global__ void mean_kernel(const float* __restrict__ x) {
    int b = blockIdx.x;
    int i = threadIdx.x;            // 512 threads
    const float* xb = x + (size_t)b * TT * II + i;
    float s = 0.f;
    for (int t = 0; t < TT; t++) s += xb[(size_t)t * II];
    g_router_in[b * II + i] = s * (1.0f / (float)TT);
}

__global__ void router1_kernel(const float* __restrict__ rW1, const float* __restrict__ rb1) {
    int b = blockIdx.x;
    __shared__ float rin[II];
    for (int i = threadIdx.x; i < II; i += blockDim.x) rin[i] = g_router_in[b * II + i];
    __syncthreads();
    for (int n = threadIdx.x; n < II; n += blockDim.x) {
        float s = rb1[n];
        const float* w = rW1 + (size_t)n * II;
        for (int k = 0; k < II; k += 4) {
            float4 wv = *(const float4*)(w + k);
            s += rin[k] * wv.x + rin[k + 1] * wv.y + rin[k + 2] * wv.z + rin[k + 3] * wv.w;
        }
        // silu (accurate: routing decisions feed everything)
        float sg = 1.f / (1.f + expf(-s));
        g_router_h[b * II + n] = s * sg;
    }
}

__global__ void router2_kernel(const float* __restrict__ rW2, const float* __restrict__ rb2) {
    __shared__ float logits[BB][EE];
    __shared__ float probs[BB][EE];
    __shared__ float gate[BB][EE];
    int tid = threadIdx.x;          // 128 threads
    {
        int b = tid >> 2, e = tid & 3;
        float s = rb2[e];
        const float* w = rW2 + (size_t)e * II;
        const float* h = g_router_h + (size_t)b * II;
        for (int k = 0; k < II; k++) s += h[k] * w[k];
        logits[b][e] = s;
    }
    __syncthreads();
    if (tid < BB) {
        int b = tid;
        float m = logits[b][0];
        for (int e = 1; e < EE; e++) m = fmaxf(m, logits[b][e]);
        float pr[EE], sum = 0.f;
        for (int e = 0; e < EE; e++) { pr[e] = expf(logits[b][e] - m); sum += pr[e]; }
        for (int e = 0; e < EE; e++) { pr[e] /= sum; probs[b][e] = pr[e]; gate[b][e] = 0.f; }
        int i1 = 0;
        for (int e = 1; e < EE; e++) if (pr[e] > pr[i1]) i1 = e;      // ties -> lowest index
        int i2 = -1;
        for (int e = 0; e < EE; e++) {
            if (e == i1) continue;
            if (i2 < 0 || pr[e] > pr[i2]) i2 = e;
        }
        float ws = pr[i1] + pr[i2];
        gate[b][i1] = pr[i1] / ws;
        gate[b][i2] = pr[i2] / ws;
    }
    __syncthreads();
    if (tid == 0) {
        float lb = 0.f;
        for (int e = 0; e < EE; e++) {
            float u = 0.f;
            for (int b = 0; b < BB; b++) u += probs[b][e];
            u *= (1.f / (float)BB);
            float d = u - 1.0f / (float)EE;
            lb += d * d;
        }
        g_lb = 0.01f * (lb / (float)EE);
        int P = 0;
        int slotc[BB];
        for (int b = 0; b < BB; b++) slotc[b] = 0;
        for (int e = 0; e < EE; e++) {
            g_off[e] = P;
            for (int b = 0; b < BB; b++) {
                if (gate[b][e] > 0.f) {
                    g_pair_b[P] = b;
                    g_pair_e[P] = e;
                    g_bpair[b * 2 + slotc[b]] = P;
                    g_bw[b * 2 + slotc[b]] = gate[b][e];
                    slotc[b]++;
                    P++;
                }
            }
            g_cnt[e] = P - g_off[e];
        }
    }
}

__global__ void init_state_kernel() {
    int idx = blockIdx.x * blockDim.x + threadIdx.x;
    if (idx < NCHAIN * HH) {
        g_hbuf[0][idx] = 0.f;
        g_hbuf[1][idx] = 0.f;
        g_cbuf[idx] = 0.f;
    }
}

// ---------------- generic 128x128 reg-blocked SGEMM (C = A @ B^T + bias) ------
#define TMm 128
#define TNn 128
#define TKk 16

__device__ __forceinline__ void sgemm_block(
    const float* __restrict__ A,   // [M,K] row-major
    const float* __restrict__ Bw,  // [N,K] row-major
    float* __restrict__ C, int ldc,
    int K, int m0, int n0,
    const float* __restrict__ bias1, const float* __restrict__ bias2)
{
    __shared__ float As[TKk][TMm + 4];
    __shared__ float Bs[TKk][TNn + 4];
    int tid = threadIdx.x;       // 256
    int tx = tid & 15;
    int ty = tid >> 4;
    float acc[8][8];
#pragma unroll
    for (int i = 0; i < 8; i++)
#pragma unroll
        for (int j = 0; j < 8; j++) acc[i][j] = 0.f;

    for (int k0 = 0; k0 < K; k0 += TKk) {
#pragma unroll
        for (int it = 0; it < 2; it++) {
            int idx = tid + it * 256;           // 0..511
            int row = idx >> 2;
            int kv  = (idx & 3) * 4;
            float4 v = *(const float4*)(A + (size_t)(m0 + row) * K + k0 + kv);
            As[kv + 0][row] = v.x; As[kv + 1][row] = v.y;
            As[kv + 2][row] = v.z; As[kv + 3][row] = v.w;
        }
#pragma unroll
        for (int it = 0; it < 2; it++) {
            int idx = tid + it * 256;
            int row = idx >> 2;
            int kv  = (idx & 3) * 4;
            float4 v = *(const float4*)(Bw + (size_t)(n0 + row) * K + k0 + kv);
            Bs[kv + 0][row] = v.x; Bs[kv + 1][row] = v.y;
            Bs[kv + 2][row] = v.z; Bs[kv + 3][row] = v.w;
        }
        __syncthreads();
#pragma unroll
        for (int kk = 0; kk < TKk; kk++) {
            float a[8], b[8];
#pragma unroll
            for (int i = 0; i < 4; i++) {
                float4 v = *(const float4*)&As[kk][ty * 8 + i * 4 - (i & 1) * 4 + (i >> 1) * 0];
                (void)v;
            }
            // simple scalar loads (compiler vectorizes from padded smem)
#pragma unroll
            for (int i = 0; i < 8; i++) a[i] = As[kk][ty * 8 + i];
#pragma unroll
            for (int j = 0; j < 8; j++) b[j] = Bs[kk][tx * 8 + j];
#pragma unroll
            for (int i = 0; i < 8; i++)
#pragma unroll
                for (int j = 0; j < 8; j++) acc[i][j] += a[i] * b[j];
        }
        __syncthreads();
    }
#pragma unroll
    for (int j = 0; j < 8; j++) {
        int n = n0 + tx * 8 + j;
        float bv = 0.f;
        if (bias1) bv += bias1[n];
        if (bias2) bv += bias2[n];
#pragma unroll
        for (int i = 0; i < 8; i++) {
            int m = m0 + ty * 8 + i;
            C[(size_t)m * ldc + n] = acc[i][j] + bv;
        }
    }
}

// xp GEMM: per (pair, dir): xp = x[b] @ Wih[e,d]^T + (bih+bhh)[e,d]
__global__ __launch_bounds__(256) void xp_gemm_kernel(
    const float* __restrict__ x, const float* __restrict__ Wih,
    const float* __restrict__ bih, const float* __restrict__ bhh)
{
    int z = blockIdx.z;           // chain = p*2 + d
    int p = z >> 1, d = z & 1;
    int b = g_pair_b[p];
    int e = g_pair_e[p];
    int ed = e * 2 + d;
    const float* A  = x + (size_t)b * TT * II;
    const float* Bw = Wih + (size_t)ed * G4H * II;
    const float* b1 = bih + (size_t)ed * G4H;
    const float* b2 = bhh + (size_t)ed * G4H;
    float* C = g_xp + (size_t)z * TT * G4H;
    sgemm_block(A, Bw, C, G4H, II, blockIdx.y * TMm, blockIdx.x * TNn, b1, b2);
}

// output projection: out = combined @ Wout^T + bout
__global__ __launch_bounds__(256) void out_gemm_kernel(
    const float* __restrict__ Wout, const float* __restrict__ bout, float* __restrict__ out)
{
    sgemm_block(g_combined, Wout, out, OUTD, 2 * HH,
                blockIdx.y * TMm, blockIdx.x * TNn, bout, nullptr);
}

// ---------------- fused LSTM step: gates = xp_t + h @ Whh^T, then update ------
// grid: (16 quad-col tiles, 8 groups e*2+d), 256 threads.
// thread layout: tc = tid&31 (col in 32-wide quad tile), slot = tid>>5 (warp),
// each warp owns rows slot*4 .. slot*4+3 (warp-uniform activity guard).
__global__ __launch_bounds__(256) void lstm_step_kernel(
    const float* __restrict__ Whh, int s)
{
    int g = blockIdx.y;
    int e = g >> 1, d = g & 1;
    int cnt = g_cnt[e];
    if (cnt == 0) return;
    int off = g_off[e];
    int j0 = blockIdx.x * 32;
    int t = d ? (TT - 1 - s) : s;
    int rb = s & 1;               // read buffer parity

    __shared__ float hs[16][36];
    __shared__ float ws[16][132];

    int tid = threadIdx.x;
    int tc = tid & 31;
    int slot = tid >> 5;
    bool active = (slot * 4) < cnt;

    const float* W = Whh + (size_t)g * G4H * HH;
    const float* hread = g_hbuf[rb];

    float acc[4][4];
#pragma unroll
    for (int i = 0; i < 4; i++)
#pragma unroll
        for (int j = 0; j < 4; j++) acc[i][j] = 0.f;

    for (int k0 = 0; k0 < HH; k0 += 16) {
        if (tid < 128) {
            int row = tid >> 2;
            int kv  = (tid & 3) * 4;
            float4 v = make_float4(0.f, 0.f, 0.f, 0.f);
            if (row < cnt) {
                int chain = (off + row) * 2 + d;
                v = *(const float4*)(hread + (size_t)chain * HH + k0 + kv);
            }
            hs[kv + 0][row] = v.x; hs[kv + 1][row] = v.y;
            hs[kv + 2][row] = v.z; hs[kv + 3][row] = v.w;
        }
#pragma unroll
        for (int it = 0; it < 2; it++) {
            int idx = tid + it * 256;   // 0..511
            int r = idx >> 2;           // 0..127: gate = r>>5, col = j0 + (r&31)
            int kv = (idx & 3) * 4;
            int gate = r >> 5;
            int col = j0 + (r & 31);
            float4 v = *(const float4*)(W + (size_t)(gate * HH + col) * HH + k0 + kv);
            ws[kv + 0][r] = v.x; ws[kv + 1][r] = v.y;
            ws[kv + 2][r] = v.z; ws[kv + 3][r] = v.w;
        }
        __syncthreads();
        if (active) {
#pragma unroll
            for (int kk = 0; kk < 16; kk++) {
                float a[4], w[4];
#pragma unroll
                for (int i = 0; i < 4; i++) a[i] = hs[kk][slot * 4 + i];
#pragma unroll
                for (int j = 0; j < 4; j++) w[j] = ws[kk][j * 32 + tc];
#pragma unroll
                for (int i = 0; i < 4; i++)
#pragma unroll
                    for (int j = 0; j < 4; j++) acc[i][j] += a[i] * w[j];
            }
        }
        __syncthreads();
    }

    int j = j0 + tc;
    float* hwrite = g_hbuf[rb ^ 1];
#pragma unroll
    for (int ri = 0; ri < 4; ri++) {
        int r = slot * 4 + ri;
        if (r < cnt) {
            int p = off + r;
            int chain = p * 2 + d;
            const float* xpt = g_xp + ((size_t)chain * TT + t) * G4H;
            float gi = xpt[0 * HH + j] + acc[ri][0];
            float gf = xpt[1 * HH + j] + acc[ri][1];
            float gg = xpt[2 * HH + j] + acc[ri][2];
            float go = xpt[3 * HH + j] + acc[ri][3];
            float iv = sigmoid_fast(gi);
            float fv = sigmoid_fast(gf);
            float gv = __tanhf(gg);
            float ov = sigmoid_fast(go);
            size_t cidx = (size_t)chain * HH + j;
            float cv = fv * g_cbuf[cidx] + iv * gv;
            g_cbuf[cidx] = cv;
            float hv = ov * __tanhf(cv);
            hwrite[cidx] = hv;
            g_hout[((size_t)p * TT + t) * (2 * HH) + d * HH + j] = hv;
        }
    }
}

// ---------------- combine gated experts --------------------------------------
__global__ void combine_kernel() {
    size_t idx = (size_t)blockIdx.x * blockDim.x + threadIdx.x;
    if (idx >= (size_t)BB * TT * 2 * HH) return;
    int j = (int)(idx & (2 * HH - 1));
    size_t bt = idx >> 10;                 // / 1024
    int b = (int)(bt >> 9);                // / 512
    int t = (int)(bt & (TT - 1));
    int p0 = g_bpair[b * 2 + 0], p1 = g_bpair[b * 2 + 1];
    float w0 = g_bw[b * 2 + 0], w1 = g_bw[b * 2 + 1];
    g_combined[idx] = w0 * g_hout[((size_t)p0 * TT + t) * (2 * HH) + j]
                    + w1 * g_hout[((size_t)p1 * TT + t) * (2 * HH) + j];
}

__global__ void write_lb_kernel(float* out, int out_size) {
    out[out_size - 1] = g_lb;
}

// ---------------- host entry --------------------------------------------------
extern "C" void kernel_launch(void* const* d_in, const int* in_sizes, int n_in,
                              void* d_out, int out_size) {
    const float* x    = (const float*)d_in[0];
    const float* rW1  = (const float*)d_in[1];
    const float* rb1  = (const float*)d_in[2];
    const float* rW2  = (const float*)d_in[3];
    const float* rb2  = (const float*)d_in[4];
    const float* Wih  = (const float*)d_in[5];
    const float* Whh  = (const float*)d_in[6];
    const float* bih  = (const float*)d_in[7];
    const float* bhh  = (const float*)d_in[8];
    const float* Wout = (const float*)d_in[9];
    const float* bout = (const float*)d_in[10];
    float* out = (float*)d_out;
    (void)in_sizes; (void)n_in; (void)rb1;

    mean_kernel<<<BB, II>>>(x);
    router1_kernel<<<BB, 256>>>(rW1, rb1);
    router2_kernel<<<1, 128>>>(rW2, rb2);
    init_state_kernel<<<(NCHAIN * HH + 255) / 256, 256>>>();

    dim3 gxp(G4H / TNn, TT / TMm, NCHAIN);      // (16, 4, 128)
    xp_gemm_kernel<<<gxp, 256>>>(x, Wih, bih, bhh);

    for (int s = 0; s < TT; s++) {
        lstm_step_kernel<<<dim3(16, 8), 256>>>(Whh, s);
    }

    combine_kernel<<<(int)(((size_t)BB * TT * 2 * HH + 255) / 256), 256>>>();

    dim3 gout(OUTD / TNn, (BB * TT) / TMm);     // (4, 128)
    out_gemm_kernel<<<gout, 256>>>(Wout, bout, out);

    write_lb_kernel<<<1, 1>>>(out, out_size);
}

// round 3
// speedup vs baseline: 1.3893x; 1.3893x over previous
#include <cuda_runtime.h>
#include <cuda_bf16.h>
#include <cstdint>

// Problem constants
#define BB 32
#define TT 512
#define II 512
#define HH 512
#define G4H 2048
#define EE 4
#define OUTD 512
#define NPAIR 64     // B * TOPK
#define NCHAIN 128   // NPAIR * 2 directions

// ---------------- device scratch (static; no allocations allowed) -------------
__device__ __align__(16) float g_xp[(size_t)NCHAIN * TT * G4H];       // 512 MB
__device__ __align__(16) float g_hout[(size_t)NPAIR * TT * 2 * HH];   // 128 MB
__device__ __align__(16) float g_combined[(size_t)BB * TT * 2 * HH];  // 64 MB
__device__ __align__(16) float g_hbuf[2][NCHAIN * HH];
__device__ __align__(16) float g_cbuf[NCHAIN * HH];
__device__ __align__(16) float g_router_in[BB * II];
__device__ __align__(16) float g_router_h[BB * II];
__device__ int   g_pair_b[NPAIR];
__device__ int   g_pair_e[NPAIR];
__device__ int   g_off[EE];
__device__ int   g_cnt[EE];
__device__ int   g_bpair[BB * 2];
__device__ float g_bw[BB * 2];
__device__ float g_lb;

// ---------------- packed f32x2 helpers ----------------------------------------
typedef unsigned long long u64;

__device__ __forceinline__ u64 ffma2(u64 a, u64 b, u64 c) {
    u64 d;
    asm("fma.rn.f32x2 %0, %1, %2, %3;" : "=l"(d) : "l"(a), "l"(b), "l"(c));
    return d;
}
__device__ __forceinline__ float f2sum(u64 v) {
    float lo, hi;
    asm("mov.b64 {%0,%1}, %2;" : "=f"(lo), "=f"(hi) : "l"(v));
    return lo + hi;
}

// fast sigmoid via MUFU.TANH
__device__ __forceinline__ float sigmoid_fast(float x) {
    return 0.5f * __tanhf(0.5f * x) + 0.5f;
}

// ---------------- router ------------------------------------------------------
__global__ void mean_kernel(const float* __restrict__ x) {
    int b = blockIdx.x;
    int i = threadIdx.x;            // 512 threads
    const float* xb = x + (size_t)b * TT * II + i;
    float s = 0.f;
    for (int t = 0; t < TT; t++) s += xb[(size_t)t * II];
    g_router_in[b * II + i] = s * (1.0f / (float)TT);
}

__global__ void router1_kernel(const float* __restrict__ rW1, const float* __restrict__ rb1) {
    int b = blockIdx.x;
    __shared__ float rin[II];
    for (int i = threadIdx.x; i < II; i += blockDim.x) rin[i] = g_router_in[b * II + i];
    __syncthreads();
    for (int n = threadIdx.x; n < II; n += blockDim.x) {
        float s = rb1[n];
        const float* w = rW1 + (size_t)n * II;
        for (int k = 0; k < II; k += 4) {
            float4 wv = *(const float4*)(w + k);
            s += rin[k] * wv.x + rin[k + 1] * wv.y + rin[k + 2] * wv.z + rin[k + 3] * wv.w;
        }
        float sg = 1.f / (1.f + expf(-s));
        g_router_h[b * II + n] = s * sg;
    }
}

__global__ void router2_kernel(const float* __restrict__ rW2, const float* __restrict__ rb2) {
    __shared__ float logits[BB][EE];
    __shared__ float probs[BB][EE];
    __shared__ float gate[BB][EE];
    int tid = threadIdx.x;          // 128 threads
    {
        int b = tid >> 2, e = tid & 3;
        float s = rb2[e];
        const float* w = rW2 + (size_t)e * II;
        const float* h = g_router_h + (size_t)b * II;
        for (int k = 0; k < II; k++) s += h[k] * w[k];
        logits[b][e] = s;
    }
    __syncthreads();
    if (tid < BB) {
        int b = tid;
        float m = logits[b][0];
        for (int e = 1; e < EE; e++) m = fmaxf(m, logits[b][e]);
        float pr[EE], sum = 0.f;
        for (int e = 0; e < EE; e++) { pr[e] = expf(logits[b][e] - m); sum += pr[e]; }
        for (int e = 0; e < EE; e++) { pr[e] /= sum; probs[b][e] = pr[e]; gate[b][e] = 0.f; }
        int i1 = 0;
        for (int e = 1; e < EE; e++) if (pr[e] > pr[i1]) i1 = e;
        int i2 = -1;
        for (int e = 0; e < EE; e++) {
            if (e == i1) continue;
            if (i2 < 0 || pr[e] > pr[i2]) i2 = e;
        }
        float ws = pr[i1] + pr[i2];
        gate[b][i1] = pr[i1] / ws;
        gate[b][i2] = pr[i2] / ws;
    }
    __syncthreads();
    if (tid == 0) {
        float lb = 0.f;
        for (int e = 0; e < EE; e++) {
            float u = 0.f;
            for (int b = 0; b < BB; b++) u += probs[b][e];
            u *= (1.f / (float)BB);
            float d = u - 1.0f / (float)EE;
            lb += d * d;
        }
        g_lb = 0.01f * (lb / (float)EE);
        int P = 0;
        int slotc[BB];
        for (int b = 0; b < BB; b++) slotc[b] = 0;
        for (int e = 0; e < EE; e++) {
            g_off[e] = P;
            for (int b = 0; b < BB; b++) {
                if (gate[b][e] > 0.f) {
                    g_pair_b[P] = b;
                    g_pair_e[P] = e;
                    g_bpair[b * 2 + slotc[b]] = P;
                    g_bw[b * 2 + slotc[b]] = gate[b][e];
                    slotc[b]++;
                    P++;
                }
            }
            g_cnt[e] = P - g_off[e];
        }
    }
}

__global__ void init_state_kernel() {
    int idx = blockIdx.x * blockDim.x + threadIdx.x;
    if (idx < NCHAIN * HH) {
        g_hbuf[0][idx] = 0.f;
        g_hbuf[1][idx] = 0.f;
        g_cbuf[idx] = 0.f;
    }
}

// ---------- 128x128 reg-blocked SGEMM, k-packed f32x2 (C = A @ B^T + bias) -----
#define TMm 128
#define TNn 128
#define TKk 32          // k-tile (floats)

__device__ __forceinline__ void sgemm_block(
    const float* __restrict__ A,   // [M,K] row-major
    const float* __restrict__ Bw,  // [N,K] row-major
    float* __restrict__ C, int ldc,
    int K, int m0, int n0,
    const float* __restrict__ bias1, const float* __restrict__ bias2)
{
    __shared__ float2 As2[TKk / 2][TMm + 1];
    __shared__ float2 Bs2[TKk / 2][TNn + 1];
    int tid = threadIdx.x;       // 256
    int tx = tid & 15;           // col group
    int ty = tid >> 4;           // row group
    u64 acc2[8][8];
#pragma unroll
    for (int i = 0; i < 8; i++)
#pragma unroll
        for (int j = 0; j < 8; j++) acc2[i][j] = 0ull;

    for (int k0 = 0; k0 < K; k0 += TKk) {
        // load A tile: 128 rows x 32 k = 1024 float4 over 256 threads
#pragma unroll
        for (int it = 0; it < 4; it++) {
            int idx = tid + it * 256;           // 0..1023
            int row = idx >> 3;
            int kv  = (idx & 7) * 4;
            float4 v = *(const float4*)(A + (size_t)(m0 + row) * K + k0 + kv);
            int kv2 = kv >> 1;
            As2[kv2][row]     = make_float2(v.x, v.y);
            As2[kv2 + 1][row] = make_float2(v.z, v.w);
        }
#pragma unroll
        for (int it = 0; it < 4; it++) {
            int idx = tid + it * 256;
            int row = idx >> 3;
            int kv  = (idx & 7) * 4;
            float4 v = *(const float4*)(Bw + (size_t)(n0 + row) * K + k0 + kv);
            int kv2 = kv >> 1;
            Bs2[kv2][row]     = make_float2(v.x, v.y);
            Bs2[kv2 + 1][row] = make_float2(v.z, v.w);
        }
        __syncthreads();
#pragma unroll
        for (int kk2 = 0; kk2 < TKk / 2; kk2++) {
            u64 a2[8], b2[8];
#pragma unroll
            for (int i = 0; i < 8; i++) a2[i] = *(const u64*)&As2[kk2][ty + 16 * i];
#pragma unroll
            for (int j = 0; j < 8; j++) b2[j] = *(const u64*)&Bs2[kk2][tx + 16 * j];
#pragma unroll
            for (int i = 0; i < 8; i++)
#pragma unroll
                for (int j = 0; j < 8; j++) acc2[i][j] = ffma2(a2[i], b2[j], acc2[i][j]);
        }
        __syncthreads();
    }
#pragma unroll
    for (int j = 0; j < 8; j++) {
        int n = n0 + tx + 16 * j;
        float bv = 0.f;
        if (bias1) bv += bias1[n];
        if (bias2) bv += bias2[n];
#pragma unroll
        for (int i = 0; i < 8; i++) {
            int m = m0 + ty + 16 * i;
            C[(size_t)m * ldc + n] = f2sum(acc2[i][j]) + bv;
        }
    }
}

// xp GEMM: per (pair, dir): xp = x[b] @ Wih[e,d]^T + (bih+bhh)[e,d]
__global__ __launch_bounds__(256, 1) void xp_gemm_kernel(
    const float* __restrict__ x, const float* __restrict__ Wih,
    const float* __restrict__ bih, const float* __restrict__ bhh)
{
    int z = blockIdx.z;           // chain = p*2 + d
    int p = z >> 1, d = z & 1;
    int b = g_pair_b[p];
    int e = g_pair_e[p];
    int ed = e * 2 + d;
    const float* A  = x + (size_t)b * TT * II;
    const float* Bw = Wih + (size_t)ed * G4H * II;
    const float* b1 = bih + (size_t)ed * G4H;
    const float* b2 = bhh + (size_t)ed * G4H;
    float* C = g_xp + (size_t)z * TT * G4H;
    sgemm_block(A, Bw, C, G4H, II, blockIdx.y * TMm, blockIdx.x * TNn, b1, b2);
}

// output projection: out = combined @ Wout^T + bout
__global__ __launch_bounds__(256, 1) void out_gemm_kernel(
    const float* __restrict__ Wout, const float* __restrict__ bout, float* __restrict__ out)
{
    sgemm_block(g_combined, Wout, out, OUTD, 2 * HH,
                blockIdx.y * TMm, blockIdx.x * TNn, bout, nullptr);
}

// ---------------- fused LSTM step (f32x2): gates = xp_t + h @ Whh^T -----------
// grid: (16 quad-col tiles, 8 groups e*2+d), 256 threads.
// Each warp (slot) owns rows slot*4..slot*4+3 of the group's pair list.
#define LKT 32          // k-tile

__global__ __launch_bounds__(256, 1) void lstm_step_kernel(
    const float* __restrict__ Whh, int s)
{
    int g = blockIdx.y;
    int e = g >> 1, d = g & 1;
    int cnt = g_cnt[e];
    if (cnt == 0) return;
    int off = g_off[e];
    int j0 = blockIdx.x * 32;
    int t = d ? (TT - 1 - s) : s;
    int rb = s & 1;               // read buffer parity

    __shared__ float2 hs2[32][LKT / 2 + 1];    // up to 32 rows
    __shared__ float2 ws2[128][LKT / 2 + 1];   // 4 gates x 32 cols

    int tid = threadIdx.x;
    int tc = tid & 31;
    int slot = tid >> 5;
    bool active = (slot * 4) < cnt;

    const float* W = Whh + (size_t)g * G4H * HH;
    const float* hread = g_hbuf[rb];

    u64 acc2[4][4];
#pragma unroll
    for (int i = 0; i < 4; i++)
#pragma unroll
        for (int j = 0; j < 4; j++) acc2[i][j] = 0ull;

    for (int k0 = 0; k0 < HH; k0 += LKT) {
        // h tile: 32 rows x 32 k = 256 float4 over 256 threads
        {
            int row = tid >> 3;
            int kv  = (tid & 7) * 4;
            float4 v = make_float4(0.f, 0.f, 0.f, 0.f);
            if (row < cnt) {
                int chain = (off + row) * 2 + d;
                v = *(const float4*)(hread + (size_t)chain * HH + k0 + kv);
            }
            int kv2 = kv >> 1;
            hs2[row][kv2]     = make_float2(v.x, v.y);
            hs2[row][kv2 + 1] = make_float2(v.z, v.w);
        }
        // W tile: 128 gate-cols x 32 k = 1024 float4 over 256 threads
#pragma unroll
        for (int it = 0; it < 4; it++) {
            int idx = tid + it * 256;   // 0..1023
            int r = idx >> 3;           // 0..127: gate = r>>5, col = j0 + (r&31)
            int kv = (idx & 7) * 4;
            int gate = r >> 5;
            int col = j0 + (r & 31);
            float4 v = *(const float4*)(W + (size_t)(gate * HH + col) * HH + k0 + kv);
            int kv2 = kv >> 1;
            ws2[r][kv2]     = make_float2(v.x, v.y);
            ws2[r][kv2 + 1] = make_float2(v.z, v.w);
        }
        __syncthreads();
        if (active) {
#pragma unroll
            for (int kk2 = 0; kk2 < LKT / 2; kk2++) {
                u64 a2[4], w2[4];
#pragma unroll
                for (int i = 0; i < 4; i++) a2[i] = *(const u64*)&hs2[slot * 4 + i][kk2];
#pragma unroll
                for (int j = 0; j < 4; j++) w2[j] = *(const u64*)&ws2[j * 32 + tc][kk2];
#pragma unroll
                for (int i = 0; i < 4; i++)
#pragma unroll
                    for (int j = 0; j < 4; j++) acc2[i][j] = ffma2(a2[i], w2[j], acc2[i][j]);
            }
        }
        __syncthreads();
    }

    int j = j0 + tc;
    float* hwrite = g_hbuf[rb ^ 1];
#pragma unroll
    for (int ri = 0; ri < 4; ri++) {
        int r = slot * 4 + ri;
        if (r < cnt) {
            int p = off + r;
            int chain = p * 2 + d;
            const float* xpt = g_xp + ((size_t)chain * TT + t) * G4H;
            float gi = xpt[0 * HH + j] + f2sum(acc2[ri][0]);
            float gf = xpt[1 * HH + j] + f2sum(acc2[ri][1]);
            float gg = xpt[2 * HH + j] + f2sum(acc2[ri][2]);
            float go = xpt[3 * HH + j] + f2sum(acc2[ri][3]);
            float iv = sigmoid_fast(gi);
            float fv = sigmoid_fast(gf);
            float gv = __tanhf(gg);
            float ov = sigmoid_fast(go);
            size_t cidx = (size_t)chain * HH + j;
            float cv = fv * g_cbuf[cidx] + iv * gv;
            g_cbuf[cidx] = cv;
            float hv = ov * __tanhf(cv);
            hwrite[cidx] = hv;
            g_hout[((size_t)p * TT + t) * (2 * HH) + d * HH + j] = hv;
        }
    }
}

// ---------------- combine gated experts --------------------------------------
__global__ void combine_kernel() {
    size_t idx = (size_t)blockIdx.x * blockDim.x + threadIdx.x;
    if (idx >= (size_t)BB * TT * 2 * HH) return;
    int j = (int)(idx & (2 * HH - 1));
    size_t bt = idx >> 10;                 // / 1024
    int b = (int)(bt >> 9);                // / 512
    int t = (int)(bt & (TT - 1));
    int p0 = g_bpair[b * 2 + 0], p1 = g_bpair[b * 2 + 1];
    float w0 = g_bw[b * 2 + 0], w1 = g_bw[b * 2 + 1];
    g_combined[idx] = w0 * g_hout[((size_t)p0 * TT + t) * (2 * HH) + j]
                    + w1 * g_hout[((size_t)p1 * TT + t) * (2 * HH) + j];
}

__global__ void write_lb_kernel(float* out, int out_size) {
    out[out_size - 1] = g_lb;
}

// ---------------- host entry --------------------------------------------------
extern "C" void kernel_launch(void* const* d_in, const int* in_sizes, int n_in,
                              void* d_out, int out_size) {
    const float* x    = (const float*)d_in[0];
    const float* rW1  = (const float*)d_in[1];
    const float* rb1  = (const float*)d_in[2];
    const float* rW2  = (const float*)d_in[3];
    const float* rb2  = (const float*)d_in[4];
    const float* Wih  = (const float*)d_in[5];
    const float* Whh  = (const float*)d_in[6];
    const float* bih  = (const float*)d_in[7];
    const float* bhh  = (const float*)d_in[8];
    const float* Wout = (const float*)d_in[9];
    const float* bout = (const float*)d_in[10];
    float* out = (float*)d_out;
    (void)in_sizes; (void)n_in;

    mean_kernel<<<BB, II>>>(x);
    router1_kernel<<<BB, 256>>>(rW1, rb1);
    router2_kernel<<<1, 128>>>(rW2, rb2);
    init_state_kernel<<<(NCHAIN * HH + 255) / 256, 256>>>();

    dim3 gxp(G4H / TNn, TT / TMm, NCHAIN);      // (16, 4, 128)
    xp_gemm_kernel<<<gxp, 256>>>(x, Wih, bih, bhh);

    for (int s = 0; s < TT; s++) {
        lstm_step_kernel<<<dim3(16, 8), 256>>>(Whh, s);
    }

    combine_kernel<<<(int)(((size_t)BB * TT * 2 * HH + 255) / 256), 256>>>();

    dim3 gout(OUTD / TNn, (BB * TT) / TMm);     // (4, 128)
    out_gemm_kernel<<<gout, 256>>>(Wout, bout, out);

    write_lb_kernel<<<1, 1>>>(out, out_size);
}

// round 4
// speedup vs baseline: 1.4959x; 1.0767x over previous
#include <cuda_runtime.h>
#include <cuda_bf16.h>
#include <cstdint>

typedef unsigned long long u64;

// Problem constants
#define BB 32
#define TT 512
#define II 512
#define HH 512
#define G4H 2048
#define EE 4
#define OUTD 512
#define NPAIR 64     // B * TOPK
#define NCHAIN 128   // NPAIR * 2 directions
#define NBLK 128     // persistent recurrence blocks (co-resident on 148 SMs)

// ---------------- device scratch (static; no allocations allowed) -------------
__device__ __align__(16) float g_xp[(size_t)NCHAIN * TT * G4H];       // 512 MB
__device__ __align__(16) float g_hout[(size_t)NPAIR * TT * 2 * HH];   // 128 MB
__device__ __align__(16) float g_hbuf[2][NCHAIN * HH];
__device__ __align__(16) float g_router_in[BB * II];
__device__ __align__(16) float g_router_h[BB * II];
__device__ int   g_pair_b[NPAIR];
__device__ int   g_pair_e[NPAIR];
__device__ int   g_off[EE];
__device__ int   g_cnt[EE];
__device__ int   g_bpair[BB * 2];
__device__ float g_bw[BB * 2];
__device__ float g_lb;
__device__ int   g_bar;

// ---------------- packed f32x2 helpers ----------------------------------------
__device__ __forceinline__ u64 ffma2(u64 a, u64 b, u64 c) {
    u64 d;
    asm("fma.rn.f32x2 %0, %1, %2, %3;" : "=l"(d) : "l"(a), "l"(b), "l"(c));
    return d;
}
__device__ __forceinline__ float f2sum(u64 v) {
    float lo, hi;
    asm("mov.b64 {%0,%1}, %2;" : "=f"(lo), "=f"(hi) : "l"(v));
    return lo + hi;
}

__device__ __forceinline__ float sigmoid_fast(float x) {
    return 0.5f * __tanhf(0.5f * x) + 0.5f;
}

__device__ __forceinline__ int ld_acq(const int* p) {
    int v;
    asm volatile("ld.acquire.gpu.b32 %0, [%1];" : "=r"(v) : "l"(p));
    return v;
}

__device__ __forceinline__ void grid_barrier(int target) {
    __threadfence();
    __syncthreads();
    if (threadIdx.x == 0) {
        atomicAdd(&g_bar, 1);
        while (ld_acq(&g_bar) < target) __nanosleep(32);
    }
    __syncthreads();
}

// ---------------- router ------------------------------------------------------
__global__ void mean_kernel(const float* __restrict__ x) {
    int b = blockIdx.x;
    int i = threadIdx.x;            // 512 threads
    const float* xb = x + (size_t)b * TT * II + i;
    float s = 0.f;
    for (int t = 0; t < TT; t++) s += xb[(size_t)t * II];
    g_router_in[b * II + i] = s * (1.0f / (float)TT);
}

__global__ void router1_kernel(const float* __restrict__ rW1, const float* __restrict__ rb1) {
    int b = blockIdx.x;
    __shared__ float rin[II];
    for (int i = threadIdx.x; i < II; i += blockDim.x) rin[i] = g_router_in[b * II + i];
    __syncthreads();
    for (int n = threadIdx.x; n < II; n += blockDim.x) {
        float s = rb1[n];
        const float* w = rW1 + (size_t)n * II;
        for (int k = 0; k < II; k += 4) {
            float4 wv = *(const float4*)(w + k);
            s += rin[k] * wv.x + rin[k + 1] * wv.y + rin[k + 2] * wv.z + rin[k + 3] * wv.w;
        }
        float sg = 1.f / (1.f + expf(-s));
        g_router_h[b * II + n] = s * sg;
    }
}

__global__ void router2_kernel(const float* __restrict__ rW2, const float* __restrict__ rb2) {
    __shared__ float logits[BB][EE];
    __shared__ float probs[BB][EE];
    __shared__ float gate[BB][EE];
    int tid = threadIdx.x;          // 128 threads
    {
        int b = tid >> 2, e = tid & 3;
        float s = rb2[e];
        const float* w = rW2 + (size_t)e * II;
        const float* h = g_router_h + (size_t)b * II;
        for (int k = 0; k < II; k++) s += h[k] * w[k];
        logits[b][e] = s;
    }
    __syncthreads();
    if (tid < BB) {
        int b = tid;
        float m = logits[b][0];
        for (int e = 1; e < EE; e++) m = fmaxf(m, logits[b][e]);
        float pr[EE], sum = 0.f;
        for (int e = 0; e < EE; e++) { pr[e] = expf(logits[b][e] - m); sum += pr[e]; }
        for (int e = 0; e < EE; e++) { pr[e] /= sum; probs[b][e] = pr[e]; gate[b][e] = 0.f; }
        int i1 = 0;
        for (int e = 1; e < EE; e++) if (pr[e] > pr[i1]) i1 = e;
        int i2 = -1;
        for (int e = 0; e < EE; e++) {
            if (e == i1) continue;
            if (i2 < 0 || pr[e] > pr[i2]) i2 = e;
        }
        float ws = pr[i1] + pr[i2];
        gate[b][i1] = pr[i1] / ws;
        gate[b][i2] = pr[i2] / ws;
    }
    __syncthreads();
    if (tid == 0) {
        float lb = 0.f;
        for (int e = 0; e < EE; e++) {
            float u = 0.f;
            for (int b = 0; b < BB; b++) u += probs[b][e];
            u *= (1.f / (float)BB);
            float d = u - 1.0f / (float)EE;
            lb += d * d;
        }
        g_lb = 0.01f * (lb / (float)EE);
        int P = 0;
        int slotc[BB];
        for (int b = 0; b < BB; b++) slotc[b] = 0;
        for (int e = 0; e < EE; e++) {
            g_off[e] = P;
            for (int b = 0; b < BB; b++) {
                if (gate[b][e] > 0.f) {
                    g_pair_b[P] = b;
                    g_pair_e[P] = e;
                    g_bpair[b * 2 + slotc[b]] = P;
                    g_bw[b * 2 + slotc[b]] = gate[b][e];
                    slotc[b]++;
                    P++;
                }
            }
            g_cnt[e] = P - g_off[e];
        }
    }
}

__global__ void init_state_kernel() {
    int idx = blockIdx.x * blockDim.x + threadIdx.x;
    if (idx == 0) g_bar = 0;
    if (idx < NCHAIN * HH) {
        g_hbuf[0][idx] = 0.f;
        g_hbuf[1][idx] = 0.f;
    }
}

// ---------- 128x128 reg-blocked SGEMM, k-packed f32x2 (C = A @ B^T + bias) -----
#define TMm 128
#define TNn 128
#define TKk 32

__device__ __forceinline__ void sgemm_block(
    const float* __restrict__ A, const float* __restrict__ Bw,
    float* __restrict__ C, int ldc, int K, int m0, int n0,
    const float* __restrict__ bias1, const float* __restrict__ bias2)
{
    __shared__ float2 As2[TKk / 2][TMm + 1];
    __shared__ float2 Bs2[TKk / 2][TNn + 1];
    int tid = threadIdx.x;       // 256
    int tx = tid & 15;
    int ty = tid >> 4;
    u64 acc2[8][8];
#pragma unroll
    for (int i = 0; i < 8; i++)
#pragma unroll
        for (int j = 0; j < 8; j++) acc2[i][j] = 0ull;

    for (int k0 = 0; k0 < K; k0 += TKk) {
#pragma unroll
        for (int it = 0; it < 4; it++) {
            int idx = tid + it * 256;
            int row = idx >> 3;
            int kv  = (idx & 7) * 4;
            float4 v = *(const float4*)(A + (size_t)(m0 + row) * K + k0 + kv);
            int kv2 = kv >> 1;
            As2[kv2][row]     = make_float2(v.x, v.y);
            As2[kv2 + 1][row] = make_float2(v.z, v.w);
        }
#pragma unroll
        for (int it = 0; it < 4; it++) {
            int idx = tid + it * 256;
            int row = idx >> 3;
            int kv  = (idx & 7) * 4;
            float4 v = *(const float4*)(Bw + (size_t)(n0 + row) * K + k0 + kv);
            int kv2 = kv >> 1;
            Bs2[kv2][row]     = make_float2(v.x, v.y);
            Bs2[kv2 + 1][row] = make_float2(v.z, v.w);
        }
        __syncthreads();
#pragma unroll
        for (int kk2 = 0; kk2 < TKk / 2; kk2++) {
            u64 a2[8], b2[8];
#pragma unroll
            for (int i = 0; i < 8; i++) a2[i] = *(const u64*)&As2[kk2][ty + 16 * i];
#pragma unroll
            for (int j = 0; j < 8; j++) b2[j] = *(const u64*)&Bs2[kk2][tx + 16 * j];
#pragma unroll
            for (int i = 0; i < 8; i++)
#pragma unroll
                for (int j = 0; j < 8; j++) acc2[i][j] = ffma2(a2[i], b2[j], acc2[i][j]);
        }
        __syncthreads();
    }
#pragma unroll
    for (int j = 0; j < 8; j++) {
        int n = n0 + tx + 16 * j;
        float bv = 0.f;
        if (bias1) bv += bias1[n];
        if (bias2) bv += bias2[n];
#pragma unroll
        for (int i = 0; i < 8; i++) {
            int m = m0 + ty + 16 * i;
            C[(size_t)m * ldc + n] = f2sum(acc2[i][j]) + bv;
        }
    }
}

__global__ __launch_bounds__(256, 1) void xp_gemm_kernel(
    const float* __restrict__ x, const float* __restrict__ Wih,
    const float* __restrict__ bih, const float* __restrict__ bhh)
{
    int z = blockIdx.z;
    int p = z >> 1, d = z & 1;
    int b = g_pair_b[p];
    int e = g_pair_e[p];
    int ed = e * 2 + d;
    const float* A  = x + (size_t)b * TT * II;
    const float* Bw = Wih + (size_t)ed * G4H * II;
    const float* b1 = bih + (size_t)ed * G4H;
    const float* b2 = bhh + (size_t)ed * G4H;
    float* C = g_xp + (size_t)z * TT * G4H;
    sgemm_block(A, Bw, C, G4H, II, blockIdx.y * TMm, blockIdx.x * TNn, b1, b2);
}

// ---- output projection fused with gate-combine: out = (Σ w_i hout_i) @ Wout^T + bout
__global__ __launch_bounds__(256, 1) void out_gemm_fused_kernel(
    const float* __restrict__ Wout, const float* __restrict__ bout, float* __restrict__ out)
{
    const int K = 2 * HH;
    int m0 = blockIdx.y * TMm, n0 = blockIdx.x * TNn;
    __shared__ float2 As2[TKk / 2][TMm + 1];
    __shared__ float2 Bs2[TKk / 2][TNn + 1];
    int tid = threadIdx.x;
    int tx = tid & 15;
    int ty = tid >> 4;
    u64 acc2[8][8];
#pragma unroll
    for (int i = 0; i < 8; i++)
#pragma unroll
        for (int j = 0; j < 8; j++) acc2[i][j] = 0ull;

    for (int k0 = 0; k0 < K; k0 += TKk) {
#pragma unroll
        for (int it = 0; it < 4; it++) {
            int idx = tid + it * 256;
            int row = idx >> 3;
            int kv  = (idx & 7) * 4;
            int m = m0 + row;
            int b = m >> 9, t = m & (TT - 1);
            int p0 = g_bpair[b * 2 + 0], p1 = g_bpair[b * 2 + 1];
            float w0 = g_bw[b * 2 + 0],  w1 = g_bw[b * 2 + 1];
            const float* h0 = g_hout + ((size_t)p0 * TT + t) * (2 * HH) + k0 + kv;
            const float* h1 = g_hout + ((size_t)p1 * TT + t) * (2 * HH) + k0 + kv;
            float4 v0 = __ldg((const float4*)h0);
            float4 v1 = __ldg((const float4*)h1);
            float4 v = make_float4(w0 * v0.x + w1 * v1.x, w0 * v0.y + w1 * v1.y,
                                   w0 * v0.z + w1 * v1.z, w0 * v0.w + w1 * v1.w);
            int kv2 = kv >> 1;
            As2[kv2][row]     = make_float2(v.x, v.y);
            As2[kv2 + 1][row] = make_float2(v.z, v.w);
        }
#pragma unroll
        for (int it = 0; it < 4; it++) {
            int idx = tid + it * 256;
            int row = idx >> 3;
            int kv  = (idx & 7) * 4;
            float4 v = *(const float4*)(Wout + (size_t)(n0 + row) * K + k0 + kv);
            int kv2 = kv >> 1;
            Bs2[kv2][row]     = make_float2(v.x, v.y);
            Bs2[kv2 + 1][row] = make_float2(v.z, v.w);
        }
        __syncthreads();
#pragma unroll
        for (int kk2 = 0; kk2 < TKk / 2; kk2++) {
            u64 a2[8], b2[8];
#pragma unroll
            for (int i = 0; i < 8; i++) a2[i] = *(const u64*)&As2[kk2][ty + 16 * i];
#pragma unroll
            for (int j = 0; j < 8; j++) b2[j] = *(const u64*)&Bs2[kk2][tx + 16 * j];
#pragma unroll
            for (int i = 0; i < 8; i++)
#pragma unroll
                for (int j = 0; j < 8; j++) acc2[i][j] = ffma2(a2[i], b2[j], acc2[i][j]);
        }
        __syncthreads();
    }
#pragma unroll
    for (int j = 0; j < 8; j++) {
        int n = n0 + tx + 16 * j;
        float bv = bout[n];
#pragma unroll
        for (int i = 0; i < 8; i++) {
            int m = m0 + ty + 16 * i;
            out[(size_t)m * OUTD + n] = f2sum(acc2[i][j]) + bv;
        }
    }
}

// ---------------- persistent LSTM recurrence ----------------------------------
// Grid: 128 blocks = 16 col-tiles x 8 groups(e,d). 256 threads.
// Warp w owns 16 outputs: cols j0+w*4+{0..3} x 4 gates (out index = ci*4+gate).
// Lane = (row r0 in [0,LR)) x (output-half hv in [0,32/LR)); RPL rows per lane.
// c-state in registers; W/h tiles software-pipelined LDG->regs->STS.

template<int LR, int RPL>
__device__ void run_lstm(int g, int j0, int off, int cnt, const float* __restrict__ Whh) {
    constexpr int HV  = 32 / LR;
    constexpr int OPL = 16 / HV;      // outputs per lane
    constexpr int CPL = OPL / 4;      // cols per lane
    const int d = g & 1;

    __shared__ u64 ws2s[128 * 34];    // [out 0..127][kpair 0..31], stride 34 (16B-aligned)
    __shared__ u64 hs2s[32 * 33];     // [row][kpair], stride 33 (bank-clean LDS.64)

    int tid = threadIdx.x;
    int w = tid >> 5, lane = tid & 31;
    int r0 = lane % LR, hv = lane / LR;

    // static W fill pointers (8 float4 chunks/thread/ktile)
    const float* wbase[8];
    int wsrow[8];
    int fkq = tid & 15;
#pragma unroll
    for (int it = 0; it < 8; it++) {
        int idx = tid + it * 256;
        int r = idx >> 4;                      // ws2s row
        int ww = r >> 4, ci = (r >> 2) & 3, gate = r & 3;
        int grow = gate * HH + j0 + ww * 4 + ci;
        wbase[it] = Whh + (size_t)grow * HH + fkq * 4;
        wsrow[it] = r;
    }
    // h fill (2 rows/thread)
    int hrow[2], hchain[2];
#pragma unroll
    for (int it = 0; it < 2; it++) {
        int idx = tid + it * 256;
        hrow[it] = idx >> 4;
        hchain[it] = (off + hrow[it]) * 2 + d;
    }
    // compute-lane rows
    int rowc[RPL], chainc[RPL], hbase[RPL];
#pragma unroll
    for (int ri = 0; ri < RPL; ri++) {
        rowc[ri] = r0 + ri * LR;
        chainc[ri] = (off + rowc[ri]) * 2 + d;
        hbase[ri] = rowc[ri] * 33;
    }

    float c_reg[RPL][CPL];
#pragma unroll
    for (int ri = 0; ri < RPL; ri++)
#pragma unroll
        for (int cj = 0; cj < CPL; cj++) c_reg[ri][cj] = 0.f;

    for (int s = 0; s < TT; s++) {
        int rb = s & 1;
        int t = d ? (TT - 1 - s) : s;
        const float* hread = g_hbuf[rb];
        float* hwrite = g_hbuf[rb ^ 1];

        u64 acc[RPL][OPL];
#pragma unroll
        for (int ri = 0; ri < RPL; ri++)
#pragma unroll
            for (int oi = 0; oi < OPL; oi++) acc[ri][oi] = 0ull;

        float4 wreg[8];
        float4 hreg[2];
        // prologue prefetch ktile 0
#pragma unroll
        for (int it = 0; it < 8; it++) wreg[it] = __ldg((const float4*)(wbase[it]));
#pragma unroll
        for (int it = 0; it < 2; it++) {
            hreg[it] = make_float4(0.f, 0.f, 0.f, 0.f);
            if (hrow[it] < cnt)
                hreg[it] = __ldcg((const float4*)(hread + (size_t)hchain[it] * HH + fkq * 4));
        }

        for (int kt = 0; kt < 8; kt++) {
            // store tile kt
#pragma unroll
            for (int it = 0; it < 8; it++)
                *(float4*)&ws2s[wsrow[it] * 34 + fkq * 2] = wreg[it];
#pragma unroll
            for (int it = 0; it < 2; it++) {
                union { float4 f4; u64 u2[2]; } cv; cv.f4 = hreg[it];
                hs2s[hrow[it] * 33 + fkq * 2]     = cv.u2[0];
                hs2s[hrow[it] * 33 + fkq * 2 + 1] = cv.u2[1];
            }
            __syncthreads();
            // prefetch tile kt+1 (LDG latency hidden by compute below)
            if (kt < 7) {
                int k0n = (kt + 1) * 64;
#pragma unroll
                for (int it = 0; it < 8; it++) wreg[it] = __ldg((const float4*)(wbase[it] + k0n));
#pragma unroll
                for (int it = 0; it < 2; it++) {
                    hreg[it] = make_float4(0.f, 0.f, 0.f, 0.f);
                    if (hrow[it] < cnt)
                        hreg[it] = __ldcg((const float4*)(hread + (size_t)hchain[it] * HH + k0n + fkq * 4));
                }
            }
            // compute tile kt: 16 kpair-pairs
#pragma unroll
            for (int kkp = 0; kkp < 16; kkp++) {
                u64 h2[RPL][2];
#pragma unroll
                for (int ri = 0; ri < RPL; ri++) {
                    h2[ri][0] = hs2s[hbase[ri] + 2 * kkp];
                    h2[ri][1] = hs2s[hbase[ri] + 2 * kkp + 1];
                }
#pragma unroll
                for (int cj = 0; cj < CPL; cj++) {
#pragma unroll
                    for (int gate = 0; gate < 4; gate++) {
                        int oi = cj * 4 + gate;
                        int wrow = w * 16 + (hv * CPL + cj) * 4 + gate;
                        ulonglong2 wv = *(const ulonglong2*)&ws2s[wrow * 34 + 2 * kkp];
#pragma unroll
                        for (int ri = 0; ri < RPL; ri++) {
                            acc[ri][oi] = ffma2(h2[ri][0], wv.x, acc[ri][oi]);
                            acc[ri][oi] = ffma2(h2[ri][1], wv.y, acc[ri][oi]);
                        }
                    }
                }
            }
            __syncthreads();
        }

        // gate nonlinearities + state update
#pragma unroll
        for (int ri = 0; ri < RPL; ri++) {
            if (rowc[ri] < cnt) {
                const float* xpt = g_xp + ((size_t)chainc[ri] * TT + t) * G4H;
#pragma unroll
                for (int cj = 0; cj < CPL; cj++) {
                    int ci = hv * CPL + cj;
                    int j = j0 + w * 4 + ci;
                    float gi = __ldg(xpt + 0 * HH + j) + f2sum(acc[ri][cj * 4 + 0]);
                    float gf = __ldg(xpt + 1 * HH + j) + f2sum(acc[ri][cj * 4 + 1]);
                    float gg = __ldg(xpt + 2 * HH + j) + f2sum(acc[ri][cj * 4 + 2]);
                    float go = __ldg(xpt + 3 * HH + j) + f2sum(acc[ri][cj * 4 + 3]);
                    float iv = sigmoid_fast(gi);
                    float fv = sigmoid_fast(gf);
                    float gv = __tanhf(gg);
                    float ov = sigmoid_fast(go);
                    float cvv = fv * c_reg[ri][cj] + iv * gv;
                    c_reg[ri][cj] = cvv;
                    float hvv = ov * __tanhf(cvv);
                    __stcg(hwrite + (size_t)chainc[ri] * HH + j, hvv);
                    __stcg(g_hout + ((size_t)(off + rowc[ri]) * TT + t) * (2 * HH) + d * HH + j, hvv);
                }
            }
        }
        grid_barrier((s + 1) * NBLK);
    }
}

__global__ __launch_bounds__(256, 1) void lstm_persist_kernel(const float* __restrict__ Whh) {
    int bid = blockIdx.x;
    int coltile = bid & 15;
    int g = bid >> 4;
    int e = g >> 1;
    int cnt = g_cnt[e];
    int off = g_off[e];
    int j0 = coltile * 32;
    const float* W = Whh + (size_t)g * G4H * HH;
    if (cnt == 0) {
        for (int s = 0; s < TT; s++) grid_barrier((s + 1) * NBLK);
        return;
    }
    if (cnt <= 8)       run_lstm<8, 1>(g, j0, off, cnt, W);
    else if (cnt <= 16) run_lstm<8, 2>(g, j0, off, cnt, W);
    else                run_lstm<16, 2>(g, j0, off, cnt, W);
}

__global__ void write_lb_kernel(float* out, int out_size) {
    out[out_size - 1] = g_lb;
}

// ---------------- host entry --------------------------------------------------
extern "C" void kernel_launch(void* const* d_in, const int* in_sizes, int n_in,
                              void* d_out, int out_size) {
    const float* x    = (const float*)d_in[0];
    const float* rW1  = (const float*)d_in[1];
    const float* rb1  = (const float*)d_in[2];
    const float* rW2  = (const float*)d_in[3];
    const float* rb2  = (const float*)d_in[4];
    const float* Wih  = (const float*)d_in[5];
    const float* Whh  = (const float*)d_in[6];
    const float* bih  = (const float*)d_in[7];
    const float* bhh  = (const float*)d_in[8];
    const float* Wout = (const float*)d_in[9];
    const float* bout = (const float*)d_in[10];
    float* out = (float*)d_out;
    (void)in_sizes; (void)n_in;

    mean_kernel<<<BB, II>>>(x);
    router1_kernel<<<BB, 256>>>(rW1, rb1);
    router2_kernel<<<1, 128>>>(rW2, rb2);
    init_state_kernel<<<(NCHAIN * HH + 255) / 256, 256>>>();

    dim3 gxp(G4H / TNn, TT / TMm, NCHAIN);      // (16, 4, 128)
    xp_gemm_kernel<<<gxp, 256>>>(x, Wih, bih, bhh);

    lstm_persist_kernel<<<NBLK, 256>>>(Whh);

    dim3 gout(OUTD / TNn, (BB * TT) / TMm);     // (4, 128)
    out_gemm_fused_kernel<<<gout, 256>>>(Wout, bout, out);

    write_lb_kernel<<<1, 1>>>(out, out_size);
}